// round 10
// baseline (speedup 1.0000x reference)
#include <cuda_runtime.h>
#include <cuda_bf16.h>
#include <cstdint>
#include <math.h>

#define NHEADS 12
#define NWIN   1152
#define NTOK   64
#define CDIM   384
#define DH     32
#define MROWS  (NWIN * NTOK)   // 73728

typedef unsigned long long ull;

// ---------------------------------------------------------------------------
// Device-global scratch
// ---------------------------------------------------------------------------
__device__ float g_Q [MROWS * CDIM];
__device__ float g_K [MROWS * CDIM];
__device__ float g_V [MROWS * CDIM];
__device__ float g_tb[225 * NHEADS];   // 16*sigmoid(cpb) precomputed
__device__ float g_ls[NHEADS];
__device__ float g_bcat[3 * CDIM];

__device__ __nv_bfloat16 g_Ahi[MROWS * CDIM];
__device__ __nv_bfloat16 g_Alo[MROWS * CDIM];
__device__ __nv_bfloat16 g_Whi[CDIM * 1536];
__device__ __nv_bfloat16 g_Wlo[CDIM * 1536];

// ---------------------------------------------------------------------------
// helpers
// ---------------------------------------------------------------------------
__device__ __forceinline__ uint32_t smem_u32(const void* p)
{
    uint32_t a;
    asm("{ .reg .u64 t; cvta.to.shared.u64 t, %1; cvt.u32.u64 %0, t; }" : "=r"(a) : "l"(p));
    return a;
}
__device__ __forceinline__ void ldsm_x4(uint32_t r[4], uint32_t addr)
{
    asm volatile("ldmatrix.sync.aligned.m8n8.x4.shared.b16 {%0,%1,%2,%3}, [%4];"
                 : "=r"(r[0]), "=r"(r[1]), "=r"(r[2]), "=r"(r[3]) : "r"(addr));
}
__device__ __forceinline__ void ldsm_x4_t(uint32_t r[4], uint32_t addr)
{
    asm volatile("ldmatrix.sync.aligned.m8n8.x4.trans.shared.b16 {%0,%1,%2,%3}, [%4];"
                 : "=r"(r[0]), "=r"(r[1]), "=r"(r[2]), "=r"(r[3]) : "r"(addr));
}
__device__ __forceinline__ void mma_bf16(float c[4], const uint32_t a[4], const uint32_t b[2])
{
    asm volatile(
        "mma.sync.aligned.m16n8k16.row.col.f32.bf16.bf16.f32 "
        "{%0,%1,%2,%3},{%4,%5,%6,%7},{%8,%9},{%0,%1,%2,%3};"
        : "+f"(c[0]), "+f"(c[1]), "+f"(c[2]), "+f"(c[3])
        : "r"(a[0]), "r"(a[1]), "r"(a[2]), "r"(a[3]), "r"(b[0]), "r"(b[1]));
}

// f32x2 packed helpers
__device__ __forceinline__ ull fma2(ull a, ull b, ull c)
{
    ull d; asm("fma.rn.f32x2 %0, %1, %2, %3;" : "=l"(d) : "l"(a), "l"(b), "l"(c)); return d;
}
__device__ __forceinline__ ull add2(ull a, ull b)
{
    ull d; asm("add.rn.f32x2 %0, %1, %2;" : "=l"(d) : "l"(a), "l"(b)); return d;
}
__device__ __forceinline__ ull pk2(float lo, float hi)
{
    ull r; asm("mov.b64 %0, {%1, %2};" : "=l"(r) : "f"(lo), "f"(hi)); return r;
}
__device__ __forceinline__ float2 upk2(ull v)
{
    float lo, hi; asm("mov.b64 {%0, %1}, %2;" : "=f"(lo), "=f"(hi) : "l"(v)); return make_float2(lo, hi);
}

// ---------------------------------------------------------------------------
// Kernel 0a: fp32 -> (bf16 hi, bf16 lo) split
// ---------------------------------------------------------------------------
__global__ void convert_split_kernel(const float* __restrict__ src,
                                     __nv_bfloat16* __restrict__ hi,
                                     __nv_bfloat16* __restrict__ lo, int n4)
{
    int i = blockIdx.x * blockDim.x + threadIdx.x;
    if (i >= n4) return;
    float4 v = reinterpret_cast<const float4*>(src)[i];
    float vv[4] = {v.x, v.y, v.z, v.w};
    __align__(8) __nv_bfloat16 h[4], l[4];
    #pragma unroll
    for (int j = 0; j < 4; j++) {
        h[j] = __float2bfloat16_rn(vv[j]);
        l[j] = __float2bfloat16_rn(vv[j] - __bfloat162float(h[j]));
    }
    reinterpret_cast<uint2*>(hi)[i] = *reinterpret_cast<uint2*>(h);
    reinterpret_cast<uint2*>(lo)[i] = *reinterpret_cast<uint2*>(l);
}

// ---------------------------------------------------------------------------
// Kernel 0b: split W[k][n] into concatenated planes at column offset
// ---------------------------------------------------------------------------
__global__ void split_concat_kernel(const float* __restrict__ src,
                                    __nv_bfloat16* __restrict__ hi,
                                    __nv_bfloat16* __restrict__ lo,
                                    int ncols, int coloff)
{
    int i = blockIdx.x * blockDim.x + threadIdx.x;
    if (i >= 36864) return;
    int k  = i / 96;
    int n4 = (i % 96) * 4;
    float4 v = *reinterpret_cast<const float4*>(&src[(size_t)k * 384 + n4]);
    float vv[4] = {v.x, v.y, v.z, v.w};
    __align__(8) __nv_bfloat16 h[4], l[4];
    #pragma unroll
    for (int j = 0; j < 4; j++) {
        h[j] = __float2bfloat16_rn(vv[j]);
        l[j] = __float2bfloat16_rn(vv[j] - __bfloat162float(h[j]));
    }
    size_t o = (size_t)k * ncols + coloff + n4;
    *reinterpret_cast<uint2*>(&hi[o]) = *reinterpret_cast<uint2*>(h);
    *reinterpret_cast<uint2*>(&lo[o]) = *reinterpret_cast<uint2*>(l);
}

__global__ void bias_cat_kernel(const float* __restrict__ bq, const float* __restrict__ bv)
{
    int i = blockIdx.x * blockDim.x + threadIdx.x;
    if (i >= 1152) return;
    g_bcat[i] = (i < 384) ? bq[i] : ((i < 768) ? 0.f : bv[i - 768]);
}

// ---------------------------------------------------------------------------
// Kernel 1: continuous position bias MLP (stores 16*sigmoid directly)
// ---------------------------------------------------------------------------
__global__ void cpb_kernel(const float* __restrict__ w1, const float* __restrict__ b1,
                           const float* __restrict__ w2, const float* __restrict__ b2,
                           const float* __restrict__ tau)
{
    __shared__ float red[128][12];
    const int m   = blockIdx.x;
    const int tid = threadIdx.x;
    const int ai  = m / 15;
    const int bi  = m % 15;

    float x0 = (float)(bi - 7) * (8.0f / 7.0f);
    float x1 = (float)(ai - 7) * (8.0f / 7.0f);
    float s0 = (x0 > 0.f) ? 1.f : ((x0 < 0.f) ? -1.f : 0.f);
    float s1 = (x1 > 0.f) ? 1.f : ((x1 < 0.f) ? -1.f : 0.f);
    float v0 = s0 * log2f(fabsf(x0) + 1.0f) * (1.0f / 3.0f);
    float v1 = s1 * log2f(fabsf(x1) + 1.0f) * (1.0f / 3.0f);

    float p[NHEADS];
    #pragma unroll
    for (int h = 0; h < NHEADS; h++) p[h] = 0.f;

    for (int c = tid; c < 512; c += 128) {
        float hv = v0 * w1[c] + v1 * w1[512 + c] + b1[c];
        hv = fmaxf(hv, 0.0f);
        #pragma unroll
        for (int h = 0; h < NHEADS; h++) p[h] += hv * w2[c * NHEADS + h];
    }
    #pragma unroll
    for (int h = 0; h < NHEADS; h++) red[tid][h] = p[h];
    __syncthreads();

    if (tid < NHEADS) {
        float s = 0.f;
        for (int t2 = 0; t2 < 128; t2++) s += red[t2][tid];
        float v = s + b2[tid];
        g_tb[m * NHEADS + tid] = 16.0f / (1.0f + expf(-v));   // sigmoid hoisted
        if (m == 0) g_ls[tid] = fmaxf(tau[tid] + 2.302585092994046f, 0.01f);
    }
}

// ---------------------------------------------------------------------------
// Kernel 2: double-buffered split-bf16 GEMM (unchanged from round 9)
// ---------------------------------------------------------------------------
__global__ __launch_bounds__(256, 2) void gemm_db_kernel(
    const __nv_bfloat16* __restrict__ Ahi, const __nv_bfloat16* __restrict__ Alo,
    const __nv_bfloat16* __restrict__ Bhi, const __nv_bfloat16* __restrict__ Blo,
    const float* __restrict__ bias,
    float* C0, float* C1, float* C2, int Ntot)
{
    __shared__ __align__(16) __nv_bfloat16 As[2][128][40];
    __shared__ __align__(16) __nv_bfloat16 Bs[2][32][136];

    const int tid  = threadIdx.x;
    const int lane = tid & 31;
    const int warp = tid >> 5;
    const int wm   = warp >> 2;
    const int wn   = warp & 3;
    const int rb   = blockIdx.y * 128;
    const int cb   = blockIdx.x * 128;
    const int gid  = cb / 384;
    float* C = (gid == 0) ? C0 : ((gid == 1) ? C1 : C2);

    const int ar = tid >> 1;
    const int ac = (tid & 1) * 16;
    const int br = tid >> 3;
    const int bc = (tid & 7) * 16;

    const int g  = lane >> 3;
    const int lr = lane & 7;
    const int a_row  = wm * 64 + lr + (g & 1) * 8;
    const int a_col  = (g >> 1) * 8;
    const int b_krow = lr + (g & 1) * 8;
    const int b_ncol = wn * 32 + (g >> 1) * 8;

    float acc[4][4][4];
    #pragma unroll
    for (int mi = 0; mi < 4; mi++)
        #pragma unroll
        for (int ni = 0; ni < 4; ni++)
            #pragma unroll
            for (int q = 0; q < 4; q++) acc[mi][ni][q] = 0.f;

    int4 aR0, aR1, bR0, bR1;
    {
        const __nv_bfloat16* ga = &Ahi[(size_t)(rb + ar) * 384 + ac];
        aR0 = *reinterpret_cast<const int4*>(ga);
        aR1 = *reinterpret_cast<const int4*>(ga + 8);
        const __nv_bfloat16* gb = &Bhi[(size_t)br * Ntot + cb + bc];
        bR0 = *reinterpret_cast<const int4*>(gb);
        bR1 = *reinterpret_cast<const int4*>(gb + 8);
    }

    const uint32_t asb = smem_u32(&As[0][0][0]);
    const uint32_t bsb = smem_u32(&Bs[0][0][0]);

    for (int c = 0; c < 36; c++) {
        const int buf = c & 1;
        *reinterpret_cast<int4*>(&As[buf][ar][ac])     = aR0;
        *reinterpret_cast<int4*>(&As[buf][ar][ac + 8]) = aR1;
        *reinterpret_cast<int4*>(&Bs[buf][br][bc])     = bR0;
        *reinterpret_cast<int4*>(&Bs[buf][br][bc + 8]) = bR1;
        __syncthreads();

        if (c + 1 < 36) {
            const int nc   = c + 1;
            const int phse = nc / 12;
            const int kl   = (nc % 12) * 32;
            const __nv_bfloat16* pA = (phse < 2) ? Ahi : Alo;
            const __nv_bfloat16* pB = (phse == 1) ? Blo : Bhi;
            const __nv_bfloat16* ga = &pA[(size_t)(rb + ar) * 384 + kl + ac];
            aR0 = *reinterpret_cast<const int4*>(ga);
            aR1 = *reinterpret_cast<const int4*>(ga + 8);
            const __nv_bfloat16* gb = &pB[(size_t)(kl + br) * Ntot + cb + bc];
            bR0 = *reinterpret_cast<const int4*>(gb);
            bR1 = *reinterpret_cast<const int4*>(gb + 8);
        }

        const uint32_t sA = asb + buf * 10240;
        const uint32_t sB = bsb + buf * 8704;
        #pragma unroll
        for (int ks = 0; ks < 2; ks++) {
            uint32_t af[4][4];
            #pragma unroll
            for (int mi = 0; mi < 4; mi++)
                ldsm_x4(af[mi], sA + ((a_row + mi * 16) * 40 + ks * 16 + a_col) * 2);
            uint32_t bf_[2][4];
            #pragma unroll
            for (int nt = 0; nt < 2; nt++)
                ldsm_x4_t(bf_[nt], sB + ((ks * 16 + b_krow) * 136 + b_ncol + nt * 16) * 2);
            #pragma unroll
            for (int mi = 0; mi < 4; mi++)
                #pragma unroll
                for (int ni = 0; ni < 4; ni++)
                    mma_bf16(acc[mi][ni], af[mi], &bf_[ni >> 1][(ni & 1) * 2]);
        }
    }

    #pragma unroll
    for (int mi = 0; mi < 4; mi++) {
        #pragma unroll
        for (int ni = 0; ni < 4; ni++) {
            int r    = rb + wm * 64 + mi * 16 + (lane >> 2);
            int ccat = cb + wn * 32 + ni * 8 + (lane & 3) * 2;
            int cc   = ccat - gid * 384;
            float b0 = bias[ccat];
            float b1 = bias[ccat + 1];
            float2 v0 = make_float2(acc[mi][ni][0] + b0, acc[mi][ni][1] + b1);
            float2 v1 = make_float2(acc[mi][ni][2] + b0, acc[mi][ni][3] + b1);
            *reinterpret_cast<float2*>(&C[(size_t)r * 384 + cc])       = v0;
            *reinterpret_cast<float2*>(&C[(size_t)(r + 8) * 384 + cc]) = v1;
        }
    }
}

// ---------------------------------------------------------------------------
// Kernel 3: attention, 256 threads/block, thread = (row i = tid>>2, quarter).
// Logits+mask+softmax fully in registers (quad shfl reductions).
// grid = (1152, 12), block = 256
// ---------------------------------------------------------------------------
#define AT_STRIDE 68

__global__ __launch_bounds__(256, 2) void attn_kernel(const float* __restrict__ mask)
{
    __shared__ float qs [NTOK * DH];
    __shared__ float kss[NTOK * DH];
    __shared__ float vss[NTOK * DH];
    __shared__ float at [NTOK * AT_STRIDE];
    __shared__ float kn [NTOK];
    __shared__ float tbs[225];

    const int b   = blockIdx.x;
    const int h   = blockIdx.y;
    const int tid = threadIdx.x;
    const size_t base = (size_t)b * NTOK * CDIM + h * DH;

    for (int idx = tid; idx < 512; idx += 256) {
        int n = idx >> 3;
        int d = (idx & 7) << 2;
        size_t ga = base + (size_t)n * CDIM + d;
        *reinterpret_cast<float4*>(&qs [n * DH + d]) = *reinterpret_cast<const float4*>(&g_Q[ga]);
        *reinterpret_cast<float4*>(&kss[n * DH + d]) = *reinterpret_cast<const float4*>(&g_K[ga]);
        *reinterpret_cast<float4*>(&vss[n * DH + d]) = *reinterpret_cast<const float4*>(&g_V[ga]);
    }
    for (int i = tid; i < 225; i += 256) tbs[i] = g_tb[i * NHEADS + h];
    const float ls = g_ls[h];
    __syncthreads();

    // K norms
    if (tid < 64) {
        const ulonglong2* p = reinterpret_cast<const ulonglong2*>(&kss[tid * DH]);
        ull a0 = 0ull, a1 = 0ull;
        #pragma unroll
        for (int u = 0; u < 8; u++) {
            ulonglong2 v = p[u];
            a0 = fma2(v.x, v.x, a0);
            a1 = fma2(v.y, v.y, a1);
        }
        float2 s2 = upk2(add2(a0, a1));
        kn[tid] = sqrtf(s2.x + s2.y);
    }
    __syncthreads();

    const int i  = tid >> 2;      // row 0..63
    const int cq = tid & 3;       // quarter

    // ---- logits (16 cols per thread) + mask, kept in registers ----
    float lg[16];
    {
        ull q2[16];
        ull n0 = 0ull, n1 = 0ull;
        {
            const ulonglong2* qp = reinterpret_cast<const ulonglong2*>(&qs[i * DH]);
            #pragma unroll
            for (int u = 0; u < 8; u++) {
                ulonglong2 v = qp[u];
                q2[2 * u] = v.x; q2[2 * u + 1] = v.y;
                n0 = fma2(v.x, v.x, n0);
                n1 = fma2(v.y, v.y, n1);
            }
        }
        float2 ns = upk2(add2(n0, n1));
        const float qni = sqrtf(ns.x + ns.y);

        float4 mrow[4];
        {
            const float4* mp = reinterpret_cast<const float4*>(
                mask + (size_t)b * 4096 + i * 64 + cq * 16);
            #pragma unroll
            for (int u = 0; u < 4; u++) mrow[u] = mp[u];
        }
        const float* mv = reinterpret_cast<const float*>(mrow);

        const int ri = i >> 3, ci = i & 7;
        #pragma unroll 4
        for (int jj = 0; jj < 16; jj++) {
            const int j = cq * 16 + jj;
            const ulonglong2* kp = reinterpret_cast<const ulonglong2*>(&kss[j * DH]);
            ull a0 = 0ull, a1 = 0ull, a2 = 0ull, a3 = 0ull;
            #pragma unroll
            for (int u = 0; u < 4; u++) {
                ulonglong2 v0 = kp[2 * u];
                ulonglong2 v1 = kp[2 * u + 1];
                a0 = fma2(q2[4 * u    ], v0.x, a0);
                a1 = fma2(q2[4 * u + 1], v0.y, a1);
                a2 = fma2(q2[4 * u + 2], v1.x, a2);
                a3 = fma2(q2[4 * u + 3], v1.y, a3);
            }
            float2 s2 = upk2(add2(add2(a0, a1), add2(a2, a3)));
            float dot = s2.x + s2.y;
            float den = fmaxf(qni * kn[j], 1e-6f);
            int idx = ((ri - (j >> 3)) + 7) * 15 + (ci - (j & 7)) + 7;
            lg[jj] = dot / den * ls + tbs[idx] + mv[jj];
        }
    }

    // ---- softmax in registers (quad reduction) ----
    {
        float mx = lg[0];
        #pragma unroll
        for (int jj = 1; jj < 16; jj++) mx = fmaxf(mx, lg[jj]);
        mx = fmaxf(mx, __shfl_xor_sync(0xffffffffu, mx, 1));
        mx = fmaxf(mx, __shfl_xor_sync(0xffffffffu, mx, 2));
        float s = 0.f;
        #pragma unroll
        for (int jj = 0; jj < 16; jj++) { lg[jj] = __expf(lg[jj] - mx); s += lg[jj]; }
        s += __shfl_xor_sync(0xffffffffu, s, 1);
        s += __shfl_xor_sync(0xffffffffu, s, 2);
        const float inv = 1.0f / s;
        float* arow = &at[i * AT_STRIDE + cq * 16];
        #pragma unroll
        for (int u = 0; u < 4; u++) {
            float4 v = make_float4(lg[4 * u] * inv, lg[4 * u + 1] * inv,
                                   lg[4 * u + 2] * inv, lg[4 * u + 3] * inv);
            *reinterpret_cast<float4*>(&arow[4 * u]) = v;
        }
    }
    __syncwarp();   // row quad lives in this warp; at row fully written

    // ---- AV: thread covers 8 d-cols of row i ----
    {
        const int d0 = cq * 8;
        ull acc2[4];
        #pragma unroll
        for (int u = 0; u < 4; u++) acc2[u] = 0ull;
        const float* prow = &at[i * AT_STRIDE];
        #pragma unroll 4
        for (int j = 0; j < 64; j++) {
            float p = prow[j];
            ull p2 = pk2(p, p);
            const ulonglong2* vp = reinterpret_cast<const ulonglong2*>(&vss[j * DH + d0]);
            ulonglong2 v = vp[0];
            acc2[0] = fma2(p2, v.x, acc2[0]);
            acc2[1] = fma2(p2, v.y, acc2[1]);
            ulonglong2 v2 = vp[1];
            acc2[2] = fma2(p2, v2.x, acc2[2]);
            acc2[3] = fma2(p2, v2.y, acc2[3]);
        }
        __align__(16) __nv_bfloat16 hh[8], ll[8];
        #pragma unroll
        for (int u = 0; u < 4; u++) {
            float2 f = upk2(acc2[u]);
            __nv_bfloat16 h0 = __float2bfloat16_rn(f.x);
            __nv_bfloat16 h1 = __float2bfloat16_rn(f.y);
            hh[2 * u]     = h0;
            hh[2 * u + 1] = h1;
            ll[2 * u]     = __float2bfloat16_rn(f.x - __bfloat162float(h0));
            ll[2 * u + 1] = __float2bfloat16_rn(f.y - __bfloat162float(h1));
        }
        size_t ob = (size_t)(b * NTOK + i) * CDIM + h * DH + d0;
        *reinterpret_cast<uint4*>(&g_Ahi[ob]) = *reinterpret_cast<uint4*>(hh);
        *reinterpret_cast<uint4*>(&g_Alo[ob]) = *reinterpret_cast<uint4*>(ll);
    }
}

// ---------------------------------------------------------------------------
// Launch
// ---------------------------------------------------------------------------
extern "C" void kernel_launch(void* const* d_in, const int* in_sizes, int n_in,
                              void* d_out, int out_size)
{
    (void)in_sizes; (void)n_in; (void)out_size;
    const float* x     = (const float*)d_in[0];
    const float* mask  = (const float*)d_in[1];
    const float* wq    = (const float*)d_in[2];
    const float* bq    = (const float*)d_in[3];
    const float* wk    = (const float*)d_in[4];
    const float* wv    = (const float*)d_in[5];
    const float* bv    = (const float*)d_in[6];
    const float* cw1   = (const float*)d_in[7];
    const float* cb1   = (const float*)d_in[8];
    const float* cw2   = (const float*)d_in[9];
    const float* cb2   = (const float*)d_in[10];
    const float* tau   = (const float*)d_in[11];
    const float* wproj = (const float*)d_in[12];
    const float* bproj = (const float*)d_in[13];
    float* out = (float*)d_out;

    float *pQ, *pK, *pV, *pBcat;
    __nv_bfloat16 *pAhi, *pAlo, *pWhi, *pWlo;
    cudaGetSymbolAddress((void**)&pQ,    g_Q);
    cudaGetSymbolAddress((void**)&pK,    g_K);
    cudaGetSymbolAddress((void**)&pV,    g_V);
    cudaGetSymbolAddress((void**)&pBcat, g_bcat);
    cudaGetSymbolAddress((void**)&pAhi,  g_Ahi);
    cudaGetSymbolAddress((void**)&pAlo,  g_Alo);
    cudaGetSymbolAddress((void**)&pWhi,  g_Whi);
    cudaGetSymbolAddress((void**)&pWlo,  g_Wlo);

    const int xn4 = MROWS * CDIM / 4;
    const int PROJ_OFF = CDIM * 1152;

    convert_split_kernel<<<(xn4 + 255) / 256, 256>>>(x, pAhi, pAlo, xn4);
    split_concat_kernel<<<144, 256>>>(wq, pWhi, pWlo, 1152, 0);
    split_concat_kernel<<<144, 256>>>(wk, pWhi, pWlo, 1152, 384);
    split_concat_kernel<<<144, 256>>>(wv, pWhi, pWlo, 1152, 768);
    bias_cat_kernel<<<5, 256>>>(bq, bv);

    gemm_db_kernel<<<dim3(9, MROWS / 128), 256>>>(
        pAhi, pAlo, pWhi, pWlo, pBcat, pQ, pK, pV, 1152);

    cpb_kernel<<<225, 128>>>(cw1, cb1, cw2, cb2, tau);
    attn_kernel<<<dim3(NWIN, NHEADS), 256>>>(mask);

    split_concat_kernel<<<144, 256>>>(wproj, pWhi + PROJ_OFF, pWlo + PROJ_OFF, 384, 0);
    gemm_db_kernel<<<dim3(3, MROWS / 128), 256>>>(
        pAhi, pAlo, pWhi + PROJ_OFF, pWlo + PROJ_OFF, bproj, out, nullptr, nullptr, 384);
}

// round 11
// speedup vs baseline: 1.7198x; 1.7198x over previous
#include <cuda_runtime.h>
#include <cuda_fp16.h>
#include <cstdint>
#include <math.h>

#define NHEADS 12
#define NWIN   1152
#define NTOK   64
#define CDIM   384
#define DH     32
#define MROWS  (NWIN * NTOK)   // 73728

typedef unsigned long long ull;

// ---------------------------------------------------------------------------
// Device-global scratch
// ---------------------------------------------------------------------------
__device__ float g_Q [MROWS * CDIM];
__device__ float g_K [MROWS * CDIM];
__device__ float g_V [MROWS * CDIM];
__device__ float g_tb[225 * NHEADS];   // 16*sigmoid(cpb) precomputed
__device__ float g_ls[NHEADS];
__device__ float g_bcat[3 * CDIM];

__device__ __half g_Ahi[MROWS * CDIM];
__device__ __half g_Alo[MROWS * CDIM];
// fp16 weight planes: concatenated QKV [384][1152] + proj [384][384]
__device__ __half g_W[CDIM * 1536];

// ---------------------------------------------------------------------------
// helpers
// ---------------------------------------------------------------------------
__device__ __forceinline__ uint32_t smem_u32(const void* p)
{
    uint32_t a;
    asm("{ .reg .u64 t; cvta.to.shared.u64 t, %1; cvt.u32.u64 %0, t; }" : "=r"(a) : "l"(p));
    return a;
}
__device__ __forceinline__ void ldsm_x4(uint32_t r[4], uint32_t addr)
{
    asm volatile("ldmatrix.sync.aligned.m8n8.x4.shared.b16 {%0,%1,%2,%3}, [%4];"
                 : "=r"(r[0]), "=r"(r[1]), "=r"(r[2]), "=r"(r[3]) : "r"(addr));
}
__device__ __forceinline__ void ldsm_x4_t(uint32_t r[4], uint32_t addr)
{
    asm volatile("ldmatrix.sync.aligned.m8n8.x4.trans.shared.b16 {%0,%1,%2,%3}, [%4];"
                 : "=r"(r[0]), "=r"(r[1]), "=r"(r[2]), "=r"(r[3]) : "r"(addr));
}
__device__ __forceinline__ void mma_f16(float c[4], const uint32_t a[4], const uint32_t b[2])
{
    asm volatile(
        "mma.sync.aligned.m16n8k16.row.col.f32.f16.f16.f32 "
        "{%0,%1,%2,%3},{%4,%5,%6,%7},{%8,%9},{%0,%1,%2,%3};"
        : "+f"(c[0]), "+f"(c[1]), "+f"(c[2]), "+f"(c[3])
        : "r"(a[0]), "r"(a[1]), "r"(a[2]), "r"(a[3]), "r"(b[0]), "r"(b[1]));
}

// f32x2 packed helpers
__device__ __forceinline__ ull fma2(ull a, ull b, ull c)
{
    ull d; asm("fma.rn.f32x2 %0, %1, %2, %3;" : "=l"(d) : "l"(a), "l"(b), "l"(c)); return d;
}
__device__ __forceinline__ ull add2(ull a, ull b)
{
    ull d; asm("add.rn.f32x2 %0, %1, %2;" : "=l"(d) : "l"(a), "l"(b)); return d;
}
__device__ __forceinline__ ull pk2(float lo, float hi)
{
    ull r; asm("mov.b64 %0, {%1, %2};" : "=l"(r) : "f"(lo), "f"(hi)); return r;
}
__device__ __forceinline__ float2 upk2(ull v)
{
    float lo, hi; asm("mov.b64 {%0, %1}, %2;" : "=f"(lo), "=f"(hi) : "l"(v)); return make_float2(lo, hi);
}

// ---------------------------------------------------------------------------
// Kernel 0a: fp32 -> (fp16 hi, fp16 lo) split
// ---------------------------------------------------------------------------
__global__ void convert_split_kernel(const float* __restrict__ src,
                                     __half* __restrict__ hi,
                                     __half* __restrict__ lo, int n4)
{
    int i = blockIdx.x * blockDim.x + threadIdx.x;
    if (i >= n4) return;
    float4 v = reinterpret_cast<const float4*>(src)[i];
    float vv[4] = {v.x, v.y, v.z, v.w};
    __align__(8) __half h[4], l[4];
    #pragma unroll
    for (int j = 0; j < 4; j++) {
        h[j] = __float2half_rn(vv[j]);
        l[j] = __float2half_rn(vv[j] - __half2float(h[j]));
    }
    reinterpret_cast<uint2*>(hi)[i] = *reinterpret_cast<uint2*>(h);
    reinterpret_cast<uint2*>(lo)[i] = *reinterpret_cast<uint2*>(l);
}

// ---------------------------------------------------------------------------
// Kernel 0b: W[k][n] fp32 -> fp16 plane at column offset
// ---------------------------------------------------------------------------
__global__ void w_fp16_kernel(const float* __restrict__ src,
                              __half* __restrict__ dst,
                              int ncols, int coloff)
{
    int i = blockIdx.x * blockDim.x + threadIdx.x;
    if (i >= 36864) return;
    int k  = i / 96;
    int n4 = (i % 96) * 4;
    float4 v = *reinterpret_cast<const float4*>(&src[(size_t)k * 384 + n4]);
    __align__(8) __half h[4];
    h[0] = __float2half_rn(v.x);
    h[1] = __float2half_rn(v.y);
    h[2] = __float2half_rn(v.z);
    h[3] = __float2half_rn(v.w);
    size_t o = (size_t)k * ncols + coloff + n4;
    *reinterpret_cast<uint2*>(&dst[o]) = *reinterpret_cast<uint2*>(h);
}

__global__ void bias_cat_kernel(const float* __restrict__ bq, const float* __restrict__ bv)
{
    int i = blockIdx.x * blockDim.x + threadIdx.x;
    if (i >= 1152) return;
    g_bcat[i] = (i < 384) ? bq[i] : ((i < 768) ? 0.f : bv[i - 768]);
}

// ---------------------------------------------------------------------------
// Kernel 1: continuous position bias MLP (stores 16*sigmoid directly)
// ---------------------------------------------------------------------------
__global__ void cpb_kernel(const float* __restrict__ w1, const float* __restrict__ b1,
                           const float* __restrict__ w2, const float* __restrict__ b2,
                           const float* __restrict__ tau)
{
    __shared__ float red[128][12];
    const int m   = blockIdx.x;
    const int tid = threadIdx.x;
    const int ai  = m / 15;
    const int bi  = m % 15;

    float x0 = (float)(bi - 7) * (8.0f / 7.0f);
    float x1 = (float)(ai - 7) * (8.0f / 7.0f);
    float s0 = (x0 > 0.f) ? 1.f : ((x0 < 0.f) ? -1.f : 0.f);
    float s1 = (x1 > 0.f) ? 1.f : ((x1 < 0.f) ? -1.f : 0.f);
    float v0 = s0 * log2f(fabsf(x0) + 1.0f) * (1.0f / 3.0f);
    float v1 = s1 * log2f(fabsf(x1) + 1.0f) * (1.0f / 3.0f);

    float p[NHEADS];
    #pragma unroll
    for (int h = 0; h < NHEADS; h++) p[h] = 0.f;

    for (int c = tid; c < 512; c += 128) {
        float hv = v0 * w1[c] + v1 * w1[512 + c] + b1[c];
        hv = fmaxf(hv, 0.0f);
        #pragma unroll
        for (int h = 0; h < NHEADS; h++) p[h] += hv * w2[c * NHEADS + h];
    }
    #pragma unroll
    for (int h = 0; h < NHEADS; h++) red[tid][h] = p[h];
    __syncthreads();

    if (tid < NHEADS) {
        float s = 0.f;
        for (int t2 = 0; t2 < 128; t2++) s += red[t2][tid];
        float v = s + b2[tid];
        g_tb[m * NHEADS + tid] = 16.0f / (1.0f + expf(-v));
        if (m == 0) g_ls[tid] = fmaxf(tau[tid] + 2.302585092994046f, 0.01f);
    }
}

// ---------------------------------------------------------------------------
// Kernel 2: double-buffered 2-term fp16 GEMM.
// C = (Ahi + Alo) @ W (+bias). Logical K' = 768: phase 0 Ahi*W, phase 1 Alo*W.
// Block tile 128x128, K-chunk 32 (24 chunks), 8 warps (2x4), warp tile 64x32.
// ---------------------------------------------------------------------------
__global__ __launch_bounds__(256, 2) void gemm_db_kernel(
    const __half* __restrict__ Ahi, const __half* __restrict__ Alo,
    const __half* __restrict__ W,
    const float* __restrict__ bias,
    float* C0, float* C1, float* C2, int Ntot)
{
    __shared__ __align__(16) __half As[2][128][40];
    __shared__ __align__(16) __half Bs[2][32][136];

    const int tid  = threadIdx.x;
    const int lane = tid & 31;
    const int warp = tid >> 5;
    const int wm   = warp >> 2;
    const int wn   = warp & 3;
    const int rb   = blockIdx.y * 128;
    const int cb   = blockIdx.x * 128;
    const int gid  = cb / 384;
    float* C = (gid == 0) ? C0 : ((gid == 1) ? C1 : C2);

    const int ar = tid >> 1;
    const int ac = (tid & 1) * 16;
    const int br = tid >> 3;
    const int bc = (tid & 7) * 16;

    const int g  = lane >> 3;
    const int lr = lane & 7;
    const int a_row  = wm * 64 + lr + (g & 1) * 8;
    const int a_col  = (g >> 1) * 8;
    const int b_krow = lr + (g & 1) * 8;
    const int b_ncol = wn * 32 + (g >> 1) * 8;

    float acc[4][4][4];
    #pragma unroll
    for (int mi = 0; mi < 4; mi++)
        #pragma unroll
        for (int ni = 0; ni < 4; ni++)
            #pragma unroll
            for (int q = 0; q < 4; q++) acc[mi][ni][q] = 0.f;

    int4 aR0, aR1, bR0, bR1;
    {
        const __half* ga = &Ahi[(size_t)(rb + ar) * 384 + ac];
        aR0 = *reinterpret_cast<const int4*>(ga);
        aR1 = *reinterpret_cast<const int4*>(ga + 8);
        const __half* gb = &W[(size_t)br * Ntot + cb + bc];
        bR0 = *reinterpret_cast<const int4*>(gb);
        bR1 = *reinterpret_cast<const int4*>(gb + 8);
    }

    const uint32_t asb = smem_u32(&As[0][0][0]);
    const uint32_t bsb = smem_u32(&Bs[0][0][0]);

    for (int c = 0; c < 24; c++) {
        const int buf = c & 1;
        *reinterpret_cast<int4*>(&As[buf][ar][ac])     = aR0;
        *reinterpret_cast<int4*>(&As[buf][ar][ac + 8]) = aR1;
        *reinterpret_cast<int4*>(&Bs[buf][br][bc])     = bR0;
        *reinterpret_cast<int4*>(&Bs[buf][br][bc + 8]) = bR1;
        __syncthreads();

        if (c + 1 < 24) {
            const int nc   = c + 1;
            const int kl   = (nc % 12) * 32;
            const __half* pA = (nc < 12) ? Ahi : Alo;
            const __half* ga = &pA[(size_t)(rb + ar) * 384 + kl + ac];
            aR0 = *reinterpret_cast<const int4*>(ga);
            aR1 = *reinterpret_cast<const int4*>(ga + 8);
            const __half* gb = &W[(size_t)(kl + br) * Ntot + cb + bc];
            bR0 = *reinterpret_cast<const int4*>(gb);
            bR1 = *reinterpret_cast<const int4*>(gb + 8);
        }

        const uint32_t sA = asb + buf * 10240;
        const uint32_t sB = bsb + buf * 8704;
        #pragma unroll
        for (int ks = 0; ks < 2; ks++) {
            uint32_t af[4][4];
            #pragma unroll
            for (int mi = 0; mi < 4; mi++)
                ldsm_x4(af[mi], sA + ((a_row + mi * 16) * 40 + ks * 16 + a_col) * 2);
            uint32_t bf_[2][4];
            #pragma unroll
            for (int nt = 0; nt < 2; nt++)
                ldsm_x4_t(bf_[nt], sB + ((ks * 16 + b_krow) * 136 + b_ncol + nt * 16) * 2);
            #pragma unroll
            for (int mi = 0; mi < 4; mi++)
                #pragma unroll
                for (int ni = 0; ni < 4; ni++)
                    mma_f16(acc[mi][ni], af[mi], &bf_[ni >> 1][(ni & 1) * 2]);
        }
    }

    #pragma unroll
    for (int mi = 0; mi < 4; mi++) {
        #pragma unroll
        for (int ni = 0; ni < 4; ni++) {
            int r    = rb + wm * 64 + mi * 16 + (lane >> 2);
            int ccat = cb + wn * 32 + ni * 8 + (lane & 3) * 2;
            int cc   = ccat - gid * 384;
            float b0 = bias[ccat];
            float b1 = bias[ccat + 1];
            float2 v0 = make_float2(acc[mi][ni][0] + b0, acc[mi][ni][1] + b1);
            float2 v1 = make_float2(acc[mi][ni][2] + b0, acc[mi][ni][3] + b1);
            *reinterpret_cast<float2*>(&C[(size_t)r * 384 + cc])       = v0;
            *reinterpret_cast<float2*>(&C[(size_t)(r + 8) * 384 + cc]) = v1;
        }
    }
}

// ---------------------------------------------------------------------------
// Kernel 3: per-(window, head) attention (round-9 layout), fp16 hi/lo output.
// grid = (1152, 12), block = 128
// ---------------------------------------------------------------------------
__global__ __launch_bounds__(128) void attn_kernel(const float* __restrict__ mask)
{
    __shared__ float qs [NTOK * DH];
    __shared__ float kss[NTOK * DH];
    __shared__ float vss[NTOK * DH];
    __shared__ float at [NTOK * 65];
    __shared__ float qn [NTOK];
    __shared__ float kn [NTOK];
    __shared__ float tbs[225];

    const int b   = blockIdx.x;
    const int h   = blockIdx.y;
    const int tid = threadIdx.x;
    const size_t base = (size_t)b * NTOK * CDIM + h * DH;

    for (int idx = tid; idx < 512; idx += 128) {
        int n = idx >> 3;
        int d = (idx & 7) << 2;
        size_t ga = base + (size_t)n * CDIM + d;
        *reinterpret_cast<float4*>(&qs [n * DH + d]) = *reinterpret_cast<const float4*>(&g_Q[ga]);
        *reinterpret_cast<float4*>(&kss[n * DH + d]) = *reinterpret_cast<const float4*>(&g_K[ga]);
        *reinterpret_cast<float4*>(&vss[n * DH + d]) = *reinterpret_cast<const float4*>(&g_V[ga]);
    }
    for (int i = tid; i < 225; i += 128) tbs[i] = g_tb[i * NHEADS + h];
    const float ls = g_ls[h];
    __syncthreads();

    // norms
    {
        const float* src = (tid < 64) ? qs : kss;
        int i = (tid < 64) ? tid : (tid - 64);
        const ulonglong2* p = reinterpret_cast<const ulonglong2*>(&src[i * DH]);
        ull a0 = 0ull, a1 = 0ull;
        #pragma unroll
        for (int u = 0; u < 8; u++) {
            ulonglong2 v = p[u];
            a0 = fma2(v.x, v.x, a0);
            a1 = fma2(v.y, v.y, a1);
        }
        float2 s2 = upk2(add2(a0, a1));
        float nrm = sqrtf(s2.x + s2.y);
        if (tid < 64) qn[i] = nrm; else kn[i] = nrm;
    }
    __syncthreads();

    // logits
    {
        const int i  = tid >> 1;
        const int cg = tid & 1;
        ull q2[16];
        {
            const ulonglong2* qp = reinterpret_cast<const ulonglong2*>(&qs[i * DH]);
            #pragma unroll
            for (int u = 0; u < 8; u++) { ulonglong2 v = qp[u]; q2[2 * u] = v.x; q2[2 * u + 1] = v.y; }
        }
        const float qni = qn[i];
        const int ri = i >> 3, ci = i & 7;
        #pragma unroll 4
        for (int jj = 0; jj < 32; jj++) {
            int j = cg * 32 + jj;
            const ulonglong2* kp = reinterpret_cast<const ulonglong2*>(&kss[j * DH]);
            ull a0 = 0ull, a1 = 0ull, a2 = 0ull, a3 = 0ull;
            #pragma unroll
            for (int u = 0; u < 4; u++) {
                ulonglong2 v0 = kp[2 * u];
                ulonglong2 v1 = kp[2 * u + 1];
                a0 = fma2(q2[4 * u    ], v0.x, a0);
                a1 = fma2(q2[4 * u + 1], v0.y, a1);
                a2 = fma2(q2[4 * u + 2], v1.x, a2);
                a3 = fma2(q2[4 * u + 3], v1.y, a3);
            }
            float2 s2 = upk2(add2(add2(a0, a1), add2(a2, a3)));
            float dot = s2.x + s2.y;
            float den = fmaxf(qni * kn[j], 1e-6f);
            int idx = ((ri - (j >> 3)) + 7) * 15 + (ci - (j & 7)) + 7;
            at[i * 65 + j] = dot / den * ls + tbs[idx];
        }
    }
    __syncthreads();

    // add mask
    {
        const float* mrow = mask + (size_t)b * 4096;
        for (int idx = tid; idx < 1024; idx += 128) {
            float4 mv = reinterpret_cast<const float4*>(mrow)[idx];
            int f = idx << 2;
            int i = f >> 6, j = f & 63;
            at[i * 65 + j]     += mv.x;
            at[i * 65 + j + 1] += mv.y;
            at[i * 65 + j + 2] += mv.z;
            at[i * 65 + j + 3] += mv.w;
        }
    }
    __syncthreads();

    // softmax per row
    if (tid < 64) {
        float* row = &at[tid * 65];
        float m = row[0];
        #pragma unroll 8
        for (int j = 1; j < 64; j++) m = fmaxf(m, row[j]);
        float s = 0.f;
        #pragma unroll 8
        for (int j = 0; j < 64; j++) { float e = __expf(row[j] - m); row[j] = e; s += e; }
        float inv = 1.0f / s;
        #pragma unroll 8
        for (int j = 0; j < 64; j++) row[j] *= inv;
    }
    __syncthreads();

    // AV, fp16 hi/lo output
    {
        const int i  = tid >> 1;
        const int cg = tid & 1;
        ull acc2[8];
        #pragma unroll
        for (int u = 0; u < 8; u++) acc2[u] = 0ull;
        #pragma unroll 4
        for (int j = 0; j < 64; j++) {
            float p = at[i * 65 + j];
            ull p2 = pk2(p, p);
            const ulonglong2* vp = reinterpret_cast<const ulonglong2*>(&vss[j * DH + cg * 16]);
            #pragma unroll
            for (int u = 0; u < 4; u++) {
                ulonglong2 v = vp[u];
                acc2[2 * u]     = fma2(p2, v.x, acc2[2 * u]);
                acc2[2 * u + 1] = fma2(p2, v.y, acc2[2 * u + 1]);
            }
        }
        __align__(16) __half hh[16], ll[16];
        #pragma unroll
        for (int u = 0; u < 8; u++) {
            float2 f = upk2(acc2[u]);
            __half h0 = __float2half_rn(f.x);
            __half h1 = __float2half_rn(f.y);
            hh[2 * u]     = h0;
            hh[2 * u + 1] = h1;
            ll[2 * u]     = __float2half_rn(f.x - __half2float(h0));
            ll[2 * u + 1] = __float2half_rn(f.y - __half2float(h1));
        }
        size_t ob = (size_t)(b * NTOK + i) * CDIM + h * DH + cg * 16;
        *reinterpret_cast<uint4*>(&g_Ahi[ob])     = *reinterpret_cast<uint4*>(hh);
        *reinterpret_cast<uint4*>(&g_Ahi[ob + 8]) = *reinterpret_cast<uint4*>(hh + 8);
        *reinterpret_cast<uint4*>(&g_Alo[ob])     = *reinterpret_cast<uint4*>(ll);
        *reinterpret_cast<uint4*>(&g_Alo[ob + 8]) = *reinterpret_cast<uint4*>(ll + 8);
    }
}

// ---------------------------------------------------------------------------
// Launch
// ---------------------------------------------------------------------------
extern "C" void kernel_launch(void* const* d_in, const int* in_sizes, int n_in,
                              void* d_out, int out_size)
{
    (void)in_sizes; (void)n_in; (void)out_size;
    const float* x     = (const float*)d_in[0];
    const float* mask  = (const float*)d_in[1];
    const float* wq    = (const float*)d_in[2];
    const float* bq    = (const float*)d_in[3];
    const float* wk    = (const float*)d_in[4];
    const float* wv    = (const float*)d_in[5];
    const float* bv    = (const float*)d_in[6];
    const float* cw1   = (const float*)d_in[7];
    const float* cb1   = (const float*)d_in[8];
    const float* cw2   = (const float*)d_in[9];
    const float* cb2   = (const float*)d_in[10];
    const float* tau   = (const float*)d_in[11];
    const float* wproj = (const float*)d_in[12];
    const float* bproj = (const float*)d_in[13];
    float* out = (float*)d_out;

    float *pQ, *pK, *pV, *pBcat;
    __half *pAhi, *pAlo, *pW;
    cudaGetSymbolAddress((void**)&pQ,    g_Q);
    cudaGetSymbolAddress((void**)&pK,    g_K);
    cudaGetSymbolAddress((void**)&pV,    g_V);
    cudaGetSymbolAddress((void**)&pBcat, g_bcat);
    cudaGetSymbolAddress((void**)&pAhi,  g_Ahi);
    cudaGetSymbolAddress((void**)&pAlo,  g_Alo);
    cudaGetSymbolAddress((void**)&pW,    g_W);

    const int xn4 = MROWS * CDIM / 4;
    const int PROJ_OFF = CDIM * 1152;

    convert_split_kernel<<<(xn4 + 255) / 256, 256>>>(x, pAhi, pAlo, xn4);
    w_fp16_kernel<<<144, 256>>>(wq, pW, 1152, 0);
    w_fp16_kernel<<<144, 256>>>(wk, pW, 1152, 384);
    w_fp16_kernel<<<144, 256>>>(wv, pW, 1152, 768);
    bias_cat_kernel<<<5, 256>>>(bq, bv);

    gemm_db_kernel<<<dim3(9, MROWS / 128), 256>>>(
        pAhi, pAlo, pW, pBcat, pQ, pK, pV, 1152);

    cpb_kernel<<<225, 128>>>(cw1, cb1, cw2, cb2, tau);
    attn_kernel<<<dim3(NWIN, NHEADS), 128>>>(mask);

    w_fp16_kernel<<<144, 256>>>(wproj, pW + PROJ_OFF, 384, 0);
    gemm_db_kernel<<<dim3(3, MROWS / 128), 256>>>(
        pAhi, pAlo, pW + PROJ_OFF, bproj, out, nullptr, nullptr, 384);
}